// round 16
// baseline (speedup 1.0000x reference)
#include <cuda_runtime.h>
#include <math.h>

// QuanvolutionHybrid, reduced: only feats[:,0] (patch 0, wire0 <Z>) feeds the
// FC stage. Direct 4-qubit sim, 4 threads/sample, warp-autonomous (no block
// barrier). CNOT rings removed via GF(2) conjugation (masks validated R8).
// Gate 15 dropped (identity for <Z0>, validated R11+). FC circuit collapsed
// to q = alpha*cos(ez)+beta*sin(ez) via SU(2) composition (validated R15).
// R16 delta: launch geometry 128x128 -> 64x256 (body byte-identical): halves
// CTA dispatch + per-CTA param refetch, doubles warp overlap per SMSP. Last
// untested structural knob against the 6.62-6.91us plateau.

#define SHX(v, m) __shfl_xor_sync(0xffffffffu, (v), (m))
#define SH4(v, l) __shfl_sync(0xffffffffu, (v), (l), 4)

#define WARPS_PER_BLOCK 8
#define THREADS_PER_BLOCK (WARPS_PER_BLOCK * 32)
#define SAMPLES_PER_BLOCK (THREADS_PER_BLOCK / 4)

__device__ __forceinline__ void rot_mat_fast(float phi, float theta, float omega, float4* m) {
    // PennyLane Rot(phi,theta,omega) = RZ(omega) RY(theta) RZ(phi)
    float ct, st, ca, sa, cb, sb;
    __sincosf(0.5f * theta, &st, &ct);
    __sincosf(0.5f * (phi + omega), &sa, &ca);
    __sincosf(0.5f * (phi - omega), &sb, &cb);
    m[0] = make_float4( ct * ca, -ct * sa, -st * cb, -st * sb);  // m00, m01
    m[1] = make_float4( st * cb, -st * sb,  ct * ca,  ct * sa);  // m10, m11
}

// Conjugated two-level rotation (masks validated R8).
#define GSLOT(T, GM, TM, SG, ST) {                                            \
    float apr = ar[(T) ^ (TM)], api = ai[(T) ^ (TM)];                         \
    if ((GM) != 0) { apr = SHX(apr, (GM)); api = SHX(api, (GM)); }            \
    const int side = pg ^ ((((ST) >> 1) & ((T) >> 1)) ^ ((ST) & (T) & 1));    \
    const float csr = side ? mB.z : mA.x, csi = side ? mB.w : mA.y;           \
    const float cpr = side ? mB.x : mA.z, cpi = side ? mB.y : mA.w;           \
    nr[T] = csr * ar[T] - csi * ai[T] + cpr * apr - cpi * api;                \
    ni[T] = csr * ai[T] + csi * ar[T] + cpr * api + cpi * apr; }

#define GGATE(GI, GM, TM, SG, ST) {                                           \
    const float4 mA = gw[GI][0], mB = gw[GI][1];                              \
    const int pg = (((SG) >> 1) & b1w) ^ ((SG) & b0w & 1);                    \
    float nr[4], ni[4];                                                       \
    GSLOT(0, GM, TM, SG, ST) GSLOT(1, GM, TM, SG, ST)                         \
    GSLOT(2, GM, TM, SG, ST) GSLOT(3, GM, TM, SG, ST)                         \
    ar[0] = nr[0]; ai[0] = ni[0]; ar[1] = nr[1]; ai[1] = ni[1];               \
    ar[2] = nr[2]; ai[2] = ni[2]; ar[3] = nr[3]; ai[3] = ni[3]; }

__global__ void __launch_bounds__(THREADS_PER_BLOCK, 1)
quanv_hybrid_kernel(const float* __restrict__ x,
                    const float* __restrict__ wq,    // [2,2,4,3]
                    const float* __restrict__ wfc,   // [3,3,1,3]
                    const float* __restrict__ Wout,  // [10,1]
                    const float* __restrict__ bout,  // [10]
                    float* __restrict__ out,         // [B,10]
                    int B)
{
    // Per-warp private copies: no cross-warp synchronization anywhere.
    __shared__ float4 gmw[WARPS_PER_BLOCK][25][2];
    __shared__ float  wobw[WARPS_PER_BLOCK][20];

    const int tid  = threadIdx.x;
    const int wid  = tid >> 5;
    const int lane = tid & 31;
    const int g    = tid & 3;
    const int s    = blockIdx.x * SAMPLES_PER_BLOCK + (tid >> 2);
    const int scl  = (s < B) ? s : (B - 1);

    float4 (*gw)[2] = gmw[wid];
    float*  wob     = wobw[wid];

    // Sample pixel load first (cold-miss latency overlaps prologue).
    // Lane g -> wire g angle; patch 0 offsets {0,1,28,29}.
    const int poff = (0x1D1C0100 >> (g << 3)) & 0xFF;  // {0,1,28,29}[g]
    const float pix = x[(size_t)scl * 784 + poff];

    // ---- per-warp prologue ----
    if (lane < 25) {
        const float* p = (lane < 16) ? (wq + lane * 3) : (wfc + (lane - 16) * 3);
        rot_mat_fast(p[0], p[1], p[2], gw[lane]);
    } else if (lane < 31) {
        // lanes 25..30: vector-load Wout/bout (cudaMalloc buffers: 16B aligned)
        const int q_   = lane - 25;        // 0..5
        const int half = (q_ >= 3);        // 0 = Wout, 1 = bout
        const int part = q_ - half * 3;    // 0,1,2
        const float* src = half ? bout : Wout;
        float* dst = wob + half * 10;
        if (part < 2) {
            float4 v = *(const float4*)(src + part * 4);
            dst[part * 4 + 0] = v.x; dst[part * 4 + 1] = v.y;
            dst[part * 4 + 2] = v.z; dst[part * 4 + 3] = v.w;
        } else {
            float2 v = *(const float2*)(src + 8);
            dst[8] = v.x; dst[9] = v.y;
        }
    }

    float cg_, sg_;
    __sincosf(0.5f * pix, &sg_, &cg_);
    const float c0 = SH4(cg_, 0), s0 = SH4(sg_, 0);
    const float c1 = SH4(cg_, 1), s1 = SH4(sg_, 1);
    const float c2 = SH4(cg_, 2), s2 = SH4(sg_, 2);
    const float c3 = SH4(cg_, 3), s3 = SH4(sg_, 3);

    // Layout: lane bits (b1w,b0w) = (wire0,wire3); slot bits = (wire1,wire2)
    const int b1w = (g >> 1) & 1;
    const int b0w = g & 1;

    // RX product state: amp = (-i)^pops * prod(c or s per wire bit)
    float ar[4], ai[4];
    {
        const float fl = (b1w ? s0 : c0) * (b0w ? s3 : c3);
#define MKAMP(T) {                                                            \
        const int tb1 = (T) >> 1, tb0 = (T) & 1;                              \
        float mag = fl * (tb1 ? s1 : c1) * (tb0 ? s2 : c2);                   \
        int p_ = (b1w + b0w + tb1 + tb0) & 3;                                 \
        float sv = (p_ & 2) ? -mag : mag;                                     \
        ar[T] = (p_ & 1) ? 0.f : sv;                                          \
        ai[T] = (p_ & 1) ? -sv : 0.f; }
        MKAMP(0) MKAMP(1) MKAMP(2) MKAMP(3)
#undef MKAMP
    }

    __syncwarp();   // own warp's gate matrices + weights visible

    // ---- side stream: SU(2) composition of the 9 fc gates ----
    // U = [[a, -conj(b)],[b, conj(a)]], a = m00, b = m10.
    float acr, aci, bcr, bci;
    {
        const float4 mA0 = gw[16][0], mB0 = gw[16][1];
        acr = mA0.x; aci = mA0.y; bcr = mB0.x; bci = mB0.y;
    }
#pragma unroll
    for (int gi = 17; gi < 25; gi++) {
        const float4 mA = gw[gi][0];   // a_g = (mA.x, mA.y)
        const float4 mB = gw[gi][1];   // b_g = (mB.x, mB.y)
        const float nar = mA.x*acr - mA.y*aci - (mB.x*bcr + mB.y*bci);
        const float nai = mA.x*aci + mA.y*acr - (mB.x*bci - mB.y*bcr);
        const float nbr = mB.x*acr - mB.y*aci + (mA.x*bcr + mA.y*bci);
        const float nbi = mB.x*aci + mB.y*acr + (mA.x*bci - mA.y*bcr);
        acr = nar; aci = nai; bcr = nbr; bci = nbi;
    }
    const float alpha = (acr*acr + aci*aci) - (bcr*bcr + bci*bci);
    const float beta  = 2.f * (acr*bci + aci*bcr);   // 2*Im(a*b)

    // ---- 15 conjugated rotations (gate 15 dropped: identity for <Z0>) ----
    GGATE( 0, 2, 0, 2, 0)
    GGATE( 1, 0, 2, 0, 2)
    GGATE( 2, 0, 1, 0, 1)
    GGATE( 3, 1, 0, 1, 0)
    GGATE( 4, 2, 2, 1, 3)
    GGATE( 5, 0, 3, 2, 2)
    GGATE( 6, 1, 1, 2, 3)
    GGATE( 7, 3, 2, 3, 3)
    GGATE( 8, 3, 3, 2, 3)
    GGATE( 9, 3, 1, 3, 3)
    GGATE(10, 2, 2, 3, 0)
    GGATE(11, 0, 3, 1, 1)
    GGATE(12, 0, 2, 1, 2)
    GGATE(13, 1, 3, 1, 0)
    GGATE(14, 2, 1, 2, 0)

    // ---- <Z>: measurement mask folds back to wire0 = lane bit b1w ----
    float part = ar[0]*ar[0] + ai[0]*ai[0] + ar[1]*ar[1] + ai[1]*ai[1]
               + ar[2]*ar[2] + ai[2]*ai[2] + ar[3]*ar[3] + ai[3]*ai[3];
    part = b1w ? -part : part;
    part += SHX(part, 1);
    part += SHX(part, 2);
    const float ez = part;

    // ---- collapsed FC tail: q = alpha*cos(ez) + beta*sin(ez) ----
    float ce, se;
    __sincosf(ez, &se, &ce);
    const float q = alpha * ce + beta * se;

    // ---- Linear(1,10) + log_softmax; exps split across the 4 lanes ----
    float lg[10];
#pragma unroll
    for (int k = 0; k < 10; k++) lg[k] = fmaf(q, wob[k], wob[10 + k]);
    float pse = 0.f;
#pragma unroll
    for (int k = 0; k < 3; k++) {
        int idx = g + 4 * k;
        if (idx < 10) pse += __expf(lg[idx]);
    }
    pse += SHX(pse, 1);
    pse += SHX(pse, 2);
    const float off = __logf(pse);

    if (s < B) {
        float2* ob = (float2*)(out + (size_t)s * 10);   // 40B rows, 8B aligned
        ob[g] = make_float2(lg[2 * g] - off, lg[2 * g + 1] - off);
        if (g == 0) ob[4] = make_float2(lg[8] - off, lg[9] - off);
    }
}

extern "C" void kernel_launch(void* const* d_in, const int* in_sizes, int n_in,
                              void* d_out, int out_size) {
    const float* x    = (const float*)d_in[0];   // [B,784]
    const float* wq   = (const float*)d_in[1];   // [2,2,4,3]
    const float* wfc  = (const float*)d_in[2];   // [3,3,1,3]
    const float* Wout = (const float*)d_in[3];   // [10,1]
    const float* bout = (const float*)d_in[4];   // [10]
    float* out = (float*)d_out;                  // [B,10]

    int B = in_sizes[0] / 784;
    int blocks = (B + SAMPLES_PER_BLOCK - 1) / SAMPLES_PER_BLOCK;  // 64 CTAs @ B=4096
    quanv_hybrid_kernel<<<blocks, THREADS_PER_BLOCK>>>(x, wq, wfc, Wout, bout, out, B);
}

// round 17
// speedup vs baseline: 1.2077x; 1.2077x over previous
#include <cuda_runtime.h>
#include <math.h>

// QuanvolutionHybrid — FINAL: best body at best geometry (128 CTAs x 128 thr).
// Only feats[:,0] (patch 0, wire0 <Z>) feeds the FC stage -> per batch element
// simulate ONE 4-qubit circuit (4 threads/sample, warp-autonomous blocks).
//  - CNOT rings removed via GF(2) conjugation (masks validated R8)
//  - gate 15 dropped: conjugated mask mu=2 has no wire-0 bit -> exact identity
//    for <Z0> (validated R11-R15 at ~1e-7)
//  - FC circuit collapsed to q = alpha*cos(ez)+beta*sin(ez), (alpha,beta) via
//    SU(2) composition of the 9 fixed gates (validated R15)
//  - softmax exps split across the 4 lanes of each sample group
// Geometry note (R16): 64x256 benched 8.0us -> per-SM serial chain dominates;
// 128 CTAs (1/SM on 128 SMs) is optimal spread. Measured band: 6.62-6.91us.

#define SHX(v, m) __shfl_xor_sync(0xffffffffu, (v), (m))
#define SH4(v, l) __shfl_sync(0xffffffffu, (v), (l), 4)

__device__ __forceinline__ void rot_mat_fast(float phi, float theta, float omega, float4* m) {
    // PennyLane Rot(phi,theta,omega) = RZ(omega) RY(theta) RZ(phi)
    float ct, st, ca, sa, cb, sb;
    __sincosf(0.5f * theta, &st, &ct);
    __sincosf(0.5f * (phi + omega), &sa, &ca);
    __sincosf(0.5f * (phi - omega), &sb, &cb);
    m[0] = make_float4( ct * ca, -ct * sa, -st * cb, -st * sb);  // m00, m01
    m[1] = make_float4( st * cb, -st * sb,  ct * ca,  ct * sa);  // m10, m11
}

// Conjugated two-level rotation (masks validated R8).
#define GSLOT(T, GM, TM, SG, ST) {                                            \
    float apr = ar[(T) ^ (TM)], api = ai[(T) ^ (TM)];                         \
    if ((GM) != 0) { apr = SHX(apr, (GM)); api = SHX(api, (GM)); }            \
    const int side = pg ^ ((((ST) >> 1) & ((T) >> 1)) ^ ((ST) & (T) & 1));    \
    const float csr = side ? mB.z : mA.x, csi = side ? mB.w : mA.y;           \
    const float cpr = side ? mB.x : mA.z, cpi = side ? mB.y : mA.w;           \
    nr[T] = csr * ar[T] - csi * ai[T] + cpr * apr - cpi * api;                \
    ni[T] = csr * ai[T] + csi * ar[T] + cpr * api + cpi * apr; }

#define GGATE(GI, GM, TM, SG, ST) {                                           \
    const float4 mA = gw[GI][0], mB = gw[GI][1];                              \
    const int pg = (((SG) >> 1) & b1w) ^ ((SG) & b0w & 1);                    \
    float nr[4], ni[4];                                                       \
    GSLOT(0, GM, TM, SG, ST) GSLOT(1, GM, TM, SG, ST)                         \
    GSLOT(2, GM, TM, SG, ST) GSLOT(3, GM, TM, SG, ST)                         \
    ar[0] = nr[0]; ai[0] = ni[0]; ar[1] = nr[1]; ai[1] = ni[1];               \
    ar[2] = nr[2]; ai[2] = ni[2]; ar[3] = nr[3]; ai[3] = ni[3]; }

__global__ void __launch_bounds__(128, 1)
quanv_hybrid_kernel(const float* __restrict__ x,
                    const float* __restrict__ wq,    // [2,2,4,3]
                    const float* __restrict__ wfc,   // [3,3,1,3]
                    const float* __restrict__ Wout,  // [10,1]
                    const float* __restrict__ bout,  // [10]
                    float* __restrict__ out,         // [B,10]
                    int B)
{
    // Per-warp private copies: no cross-warp synchronization anywhere.
    __shared__ float4 gmw[4][25][2];   // [0..15] quanv gates, [16..24] fc gates
    __shared__ float  wobw[4][20];     // wo[0..9], bo[0..9]

    const int tid  = threadIdx.x;
    const int wid  = tid >> 5;
    const int lane = tid & 31;
    const int g    = tid & 3;
    const int s    = blockIdx.x * 32 + (tid >> 2);
    const int scl  = (s < B) ? s : (B - 1);

    float4 (*gw)[2] = gmw[wid];
    float*  wob     = wobw[wid];

    // Sample pixel load first (cold-miss latency overlaps prologue).
    // Lane g -> wire g angle; patch 0 offsets {0,1,28,29}.
    const int poff = (0x1D1C0100 >> (g << 3)) & 0xFF;  // {0,1,28,29}[g]
    const float pix = x[(size_t)scl * 784 + poff];

    // ---- per-warp prologue ----
    if (lane < 25) {
        const float* p = (lane < 16) ? (wq + lane * 3) : (wfc + (lane - 16) * 3);
        rot_mat_fast(p[0], p[1], p[2], gw[lane]);
    } else if (lane < 31) {
        // lanes 25..30: vector-load Wout/bout (cudaMalloc buffers: 16B aligned)
        const int q_   = lane - 25;        // 0..5
        const int half = (q_ >= 3);        // 0 = Wout, 1 = bout
        const int part = q_ - half * 3;    // 0,1,2
        const float* src = half ? bout : Wout;
        float* dst = wob + half * 10;
        if (part < 2) {
            float4 v = *(const float4*)(src + part * 4);
            dst[part * 4 + 0] = v.x; dst[part * 4 + 1] = v.y;
            dst[part * 4 + 2] = v.z; dst[part * 4 + 3] = v.w;
        } else {
            float2 v = *(const float2*)(src + 8);
            dst[8] = v.x; dst[9] = v.y;
        }
    }

    float cg_, sg_;
    __sincosf(0.5f * pix, &sg_, &cg_);
    const float c0 = SH4(cg_, 0), s0 = SH4(sg_, 0);
    const float c1 = SH4(cg_, 1), s1 = SH4(sg_, 1);
    const float c2 = SH4(cg_, 2), s2 = SH4(sg_, 2);
    const float c3 = SH4(cg_, 3), s3 = SH4(sg_, 3);

    // Layout: lane bits (b1w,b0w) = (wire0,wire3); slot bits = (wire1,wire2)
    const int b1w = (g >> 1) & 1;
    const int b0w = g & 1;

    // RX product state: amp = (-i)^pops * prod(c or s per wire bit)
    float ar[4], ai[4];
    {
        const float fl = (b1w ? s0 : c0) * (b0w ? s3 : c3);
#define MKAMP(T) {                                                            \
        const int tb1 = (T) >> 1, tb0 = (T) & 1;                              \
        float mag = fl * (tb1 ? s1 : c1) * (tb0 ? s2 : c2);                   \
        int p_ = (b1w + b0w + tb1 + tb0) & 3;                                 \
        float sv = (p_ & 2) ? -mag : mag;                                     \
        ar[T] = (p_ & 1) ? 0.f : sv;                                          \
        ai[T] = (p_ & 1) ? -sv : 0.f; }
        MKAMP(0) MKAMP(1) MKAMP(2) MKAMP(3)
#undef MKAMP
    }

    __syncwarp();   // own warp's gate matrices + weights visible

    // ---- side stream: SU(2) composition of the 9 fc gates ----
    // U = [[a, -conj(b)],[b, conj(a)]], a = m00, b = m10.
    float acr, aci, bcr, bci;
    {
        const float4 mA0 = gw[16][0], mB0 = gw[16][1];
        acr = mA0.x; aci = mA0.y; bcr = mB0.x; bci = mB0.y;
    }
#pragma unroll
    for (int gi = 17; gi < 25; gi++) {
        const float4 mA = gw[gi][0];   // a_g = (mA.x, mA.y)
        const float4 mB = gw[gi][1];   // b_g = (mB.x, mB.y)
        const float nar = mA.x*acr - mA.y*aci - (mB.x*bcr + mB.y*bci);
        const float nai = mA.x*aci + mA.y*acr - (mB.x*bci - mB.y*bcr);
        const float nbr = mB.x*acr - mB.y*aci + (mA.x*bcr + mA.y*bci);
        const float nbi = mB.x*aci + mB.y*acr + (mA.x*bci - mA.y*bcr);
        acr = nar; aci = nai; bcr = nbr; bci = nbi;
    }
    const float alpha = (acr*acr + aci*aci) - (bcr*bcr + bci*bci);
    const float beta  = 2.f * (acr*bci + aci*bcr);   // 2*Im(a*b)

    // ---- 15 conjugated rotations (gate 15 dropped: identity for <Z0>) ----
    GGATE( 0, 2, 0, 2, 0)
    GGATE( 1, 0, 2, 0, 2)
    GGATE( 2, 0, 1, 0, 1)
    GGATE( 3, 1, 0, 1, 0)
    GGATE( 4, 2, 2, 1, 3)
    GGATE( 5, 0, 3, 2, 2)
    GGATE( 6, 1, 1, 2, 3)
    GGATE( 7, 3, 2, 3, 3)
    GGATE( 8, 3, 3, 2, 3)
    GGATE( 9, 3, 1, 3, 3)
    GGATE(10, 2, 2, 3, 0)
    GGATE(11, 0, 3, 1, 1)
    GGATE(12, 0, 2, 1, 2)
    GGATE(13, 1, 3, 1, 0)
    GGATE(14, 2, 1, 2, 0)

    // ---- <Z>: measurement mask folds back to wire0 = lane bit b1w ----
    float part = ar[0]*ar[0] + ai[0]*ai[0] + ar[1]*ar[1] + ai[1]*ai[1]
               + ar[2]*ar[2] + ai[2]*ai[2] + ar[3]*ar[3] + ai[3]*ai[3];
    part = b1w ? -part : part;
    part += SHX(part, 1);
    part += SHX(part, 2);
    const float ez = part;

    // ---- collapsed FC tail: q = alpha*cos(ez) + beta*sin(ez) ----
    float ce, se;
    __sincosf(ez, &se, &ce);
    const float q = alpha * ce + beta * se;

    // ---- Linear(1,10) + log_softmax; exps split across the 4 lanes ----
    float lg[10];
#pragma unroll
    for (int k = 0; k < 10; k++) lg[k] = fmaf(q, wob[k], wob[10 + k]);
    float pse = 0.f;
#pragma unroll
    for (int k = 0; k < 3; k++) {
        int idx = g + 4 * k;
        if (idx < 10) pse += __expf(lg[idx]);
    }
    pse += SHX(pse, 1);
    pse += SHX(pse, 2);
    const float off = __logf(pse);

    if (s < B) {
        float2* ob = (float2*)(out + (size_t)s * 10);   // 40B rows, 8B aligned
        ob[g] = make_float2(lg[2 * g] - off, lg[2 * g + 1] - off);
        if (g == 0) ob[4] = make_float2(lg[8] - off, lg[9] - off);
    }
}

extern "C" void kernel_launch(void* const* d_in, const int* in_sizes, int n_in,
                              void* d_out, int out_size) {
    const float* x    = (const float*)d_in[0];   // [B,784]
    const float* wq   = (const float*)d_in[1];   // [2,2,4,3]
    const float* wfc  = (const float*)d_in[2];   // [3,3,1,3]
    const float* Wout = (const float*)d_in[3];   // [10,1]
    const float* bout = (const float*)d_in[4];   // [10]
    float* out = (float*)d_out;                  // [B,10]

    int B = in_sizes[0] / 784;
    int blocks = (B + 31) / 32;                  // 32 samples per 128-thread block
    quanv_hybrid_kernel<<<blocks, 128>>>(x, wq, wfc, Wout, bout, out, B);
}